// round 16
// baseline (speedup 1.0000x reference)
#include <cuda_runtime.h>

// Fixed shapes from setup_inputs
#define HH 100
#define WW 152
#define NPAIR 76           // WW/2
#define TOTPAIR 7600       // HH*NPAIR
#define NGRP4 19           // NPAIR/4 groups of 4 consecutive pairs per row
#define TOTGRP4 1900       // HH*NGRP4
#define HWP 15200          // HH*WW
#define NCH 8
#define NPARAMS 169
#define MAXINST 400
#define OH 200
#define OW 304

// Scratch for logits (static __device__ allocation — allowed)
__device__ float g_logits[MAXINST * HWP];

typedef unsigned long long u64;

__device__ __forceinline__ u64 pk2(float a, float b) {
    u64 r;
    asm("mov.b64 %0, {%1,%2};" : "=l"(r) : "r"(__float_as_uint(a)), "r"(__float_as_uint(b)));
    return r;
}
__device__ __forceinline__ void upk2(float& a, float& b, u64 x) {
    unsigned int lo, hi;
    asm("mov.b64 {%0,%1}, %2;" : "=r"(lo), "=r"(hi) : "l"(x));
    a = __uint_as_float(lo); b = __uint_as_float(hi);
}
__device__ __forceinline__ u64 ffma2(u64 a, u64 b, u64 c) {
    u64 d;
    asm("fma.rn.f32x2 %0, %1, %2, %3;" : "=l"(d) : "l"(a), "l"(b), "l"(c));
    return d;
}
__device__ __forceinline__ u64 relu2(u64 x) {
    float a, b; upk2(a, b, x);
    a = fmaxf(a, 0.0f); b = fmaxf(b, 0.0f);
    return pk2(a, b);
}

// ---------------------------------------------------------------------------
// Kernel A: per-instance 3-layer 1x1-conv MLP -> logits [n_inst, HW].
// FOUR CONSECUTIVE pixel-pairs per thread (8 consecutive pixels, same row):
//  - feats: 2x LDG.128 per channel (16 total), double-buffered across cc
//  - stores: 2x STG.128
//  - one whole-thread guard (groups never straddle rows: 76 % 4 == 0)
// Weights transposed in shared for LDS.128 reads (from R14).
// ---------------------------------------------------------------------------
__global__ void __launch_bounds__(128, 3)
logits_kernel(const float* __restrict__ feats,     // [N, 8, H, W]
              const float* __restrict__ params,    // [n_inst, 169]
              const float* __restrict__ ilocs,     // [n_inst, 2]
              const int*   __restrict__ iminds,    // [n_inst]
              const int*   __restrict__ levels)    // [n_inst]
{
    const int inst = blockIdx.y;
    const int tid  = threadIdx.x;

    // Transposed, duplicated {w,w} packed weights (16B-aligned rows)
    __shared__ alignas(16) u64 swc[16];      // (w0[c], w1[c]) interleaved
    __shared__ alignas(16) u64 sw0t[8][8];   // [cc][c]  layer-0 feat weights
    __shared__ alignas(16) u64 sw1t[8][8];   // [k][c]   layer-1 weights
    __shared__ alignas(16) u64 sw2[8];       // layer-2 weights
    __shared__ alignas(16) u64 sb0[8];
    __shared__ alignas(16) u64 sb1[8];
    __shared__ u64 sb2;

    for (int i = tid; i < NPARAMS; i += 128) {
        const float vv = params[inst * NPARAMS + i];
        const u64 w = pk2(vv, vv);
        if (i < 80) {                       // w0: [c][j], j<10
            const int c = i / 10, j = i - c * 10;
            if (j < 2) swc[2 * c + j] = w;
            else       sw0t[j - 2][c] = w;
        } else if (i < 144) {               // w1: [c][k]
            const int idx = i - 80;
            const int c = idx / 8, k = idx - c * 8;
            sw1t[k][c] = w;
        } else if (i < 152) sw2[i - 144] = w;
        else if (i < 160)   sb0[i - 152] = w;
        else if (i < 168)   sb1[i - 160] = w;
        else                sb2 = w;
    }

    const float Lx = ilocs[2 * inst];
    const float Ly = ilocs[2 * inst + 1];
    const float inv_soi = 1.0f / (float)(64 << levels[inst]);  // SOI = 2^k -> exact
    const float* fb = feats + (size_t)iminds[inst] * (NCH * HWP);

    __syncthreads();

    const int g = blockIdx.x * 128 + tid;      // group of 4 consecutive pairs
    if (g >= TOTGRP4) return;

    const int row = g / NGRP4;
    const int jg  = g - row * NGRP4;
    const int p8  = row * WW + 8 * jg;         // first pixel (32B-aligned)

    // rel coords: pairs jj = 4jg+q, same row -> iny shared across q
    u64 inx[4];
#pragma unroll
    for (int q = 0; q < 4; q++) {
        const int jj = 4 * jg + q;
        // one rounding in subtract, exact scale by 2^-k: bit-identical to ref
        const float rx0 = (Lx - (float)(16 * jj + 4))  * inv_soi;
        const float rx1 = (Lx - (float)(16 * jj + 12)) * inv_soi;
        inx[q] = pk2(rx0, rx1);
    }
    const float ry = (Ly - (float)(row * 8 + 4)) * inv_soi;
    const u64 iny = pk2(ry, ry);

    // ---- layer 0: 10 -> 8 ----
    u64 a0[8][4];
#pragma unroll
    for (int c = 0; c < 8; c += 2) {
        const ulonglong2 bb  = *(const ulonglong2*)&sb0[c];
        const ulonglong2 wcA = *(const ulonglong2*)&swc[2 * c];      // w0,w1 of c
        const ulonglong2 wcB = *(const ulonglong2*)&swc[2 * c + 2];  // w0,w1 of c+1
#pragma unroll
        for (int q = 0; q < 4; q++) {
            a0[c][q]     = ffma2(wcA.y, iny, ffma2(wcA.x, inx[q], bb.x));
            a0[c + 1][q] = ffma2(wcB.y, iny, ffma2(wcB.x, inx[q], bb.y));
        }
    }

    // feats channels, double-buffered: 2x LDG.128 per channel
    ulonglong2 inA0 = *(const ulonglong2*)(fb + p8);       // pairs 0,1
    ulonglong2 inA1 = *(const ulonglong2*)(fb + p8 + 4);   // pairs 2,3
#pragma unroll
    for (int cc = 0; cc < 8; cc++) {
        ulonglong2 inB0, inB1;
        if (cc < 7) {
            inB0 = *(const ulonglong2*)(fb + (cc + 1) * HWP + p8);
            inB1 = *(const ulonglong2*)(fb + (cc + 1) * HWP + p8 + 4);
        }
        const u64 in[4] = { inA0.x, inA0.y, inA1.x, inA1.y };
#pragma unroll
        for (int c = 0; c < 8; c += 2) {
            const ulonglong2 ww = *(const ulonglong2*)&sw0t[cc][c];
#pragma unroll
            for (int q = 0; q < 4; q++) {
                a0[c][q]     = ffma2(ww.x, in[q], a0[c][q]);
                a0[c + 1][q] = ffma2(ww.y, in[q], a0[c + 1][q]);
            }
        }
        if (cc < 7) { inA0 = inB0; inA1 = inB1; }
    }

    // ---- layer 1: relu -> 8 -> 8 ----
    u64 a1[8][4];
#pragma unroll
    for (int c = 0; c < 8; c += 2) {
        const ulonglong2 bb = *(const ulonglong2*)&sb1[c];
#pragma unroll
        for (int q = 0; q < 4; q++) { a1[c][q] = bb.x; a1[c + 1][q] = bb.y; }
    }
#pragma unroll
    for (int k = 0; k < 8; k++) {
        u64 r[4];
#pragma unroll
        for (int q = 0; q < 4; q++) r[q] = relu2(a0[k][q]);
#pragma unroll
        for (int c = 0; c < 8; c += 2) {
            const ulonglong2 ww = *(const ulonglong2*)&sw1t[k][c];
#pragma unroll
            for (int q = 0; q < 4; q++) {
                a1[c][q]     = ffma2(ww.x, r[q], a1[c][q]);
                a1[c + 1][q] = ffma2(ww.y, r[q], a1[c + 1][q]);
            }
        }
    }

    // ---- layer 2: relu -> 8 -> 1 ----
    u64 a2[4];
    {
        const u64 b2 = sb2;
#pragma unroll
        for (int q = 0; q < 4; q++) a2[q] = b2;
    }
#pragma unroll
    for (int k = 0; k < 8; k += 2) {
        const ulonglong2 ww = *(const ulonglong2*)&sw2[k];
#pragma unroll
        for (int q = 0; q < 4; q++) {
            a2[q] = ffma2(ww.x, relu2(a1[k][q]), a2[q]);
            a2[q] = ffma2(ww.y, relu2(a1[k + 1][q]), a2[q]);
        }
    }

    float* outp = g_logits + (size_t)inst * HWP + p8;
    ulonglong2 o0; o0.x = a2[0]; o0.y = a2[1];
    ulonglong2 o1; o1.x = a2[2]; o1.y = a2[3];
    *(ulonglong2*)(outp)     = o0;
    *(ulonglong2*)(outp + 4) = o1;
}

// ---------------------------------------------------------------------------
// Kernel B: aligned_bilinear x2 upsample, one 2x4 output block per thread.
// EXACT round-10 version (measured 20.2-20.3 us three times, regs=19).
// ---------------------------------------------------------------------------
__global__ void __launch_bounds__(256)
upsample_kernel(float* __restrict__ out)
{
    const int inst = blockIdx.y;
    const int i    = blockIdx.x * 256 + threadIdx.x;
    if (i >= TOTPAIR) return;

    const int r  = i / NPAIR;
    const int j  = i - r * NPAIR;
    const int rm = (r > 0) ? r - 1 : 0;
    const int qm = (j > 0) ? (2 * j - 1) : 0;

    const float* T = g_logits + (size_t)inst * HWP;

    float A1, A2, C1, C2;
    upk2(A1, A2, *(const u64*)(T + rm * WW + 2 * j));
    upk2(C1, C2, *(const u64*)(T + r  * WW + 2 * j));
    const float A0 = T[rm * WW + qm];
    const float C0 = T[r  * WW + qm];

    float4 top, bot;
    top.x = 0.5f * (0.5f * (A0 + A1) + 0.5f * (C0 + C1));
    top.y = 0.5f * (A1 + C1);
    top.z = 0.5f * (0.5f * (A1 + A2) + 0.5f * (C1 + C2));
    top.w = 0.5f * (A2 + C2);
    bot.x = 0.5f * (C0 + C1);
    bot.y = C1;
    bot.z = 0.5f * (C1 + C2);
    bot.w = C2;

    float* ob = out + (size_t)inst * (OH * OW) + (2 * r) * OW + 4 * j;
    *(float4*)ob        = top;
    *(float4*)(ob + OW) = bot;
}

// ---------------------------------------------------------------------------
extern "C" void kernel_launch(void* const* d_in, const int* in_sizes, int n_in,
                              void* d_out, int out_size)
{
    const float* feats  = (const float*)d_in[0];
    const float* params = (const float*)d_in[1];
    const float* ilocs  = (const float*)d_in[2];
    const int*   iminds = (const int*)d_in[3];
    const int*   levels = (const int*)d_in[4];

    int n_inst = in_sizes[1] / NPARAMS;     // 400
    if (n_inst > MAXINST) n_inst = MAXINST;

    dim3 ga((TOTGRP4 + 127) / 128, n_inst);   // (15, 400), 128 threads
    logits_kernel<<<ga, 128>>>(feats, params, ilocs, iminds, levels);

    dim3 gb((TOTPAIR + 255) / 256, n_inst);   // (30, 400), 256 threads
    upsample_kernel<<<gb, 256>>>((float*)d_out);
}